// round 14
// baseline (speedup 1.0000x reference)
#include <cuda_runtime.h>
#include <cuda_bf16.h>

#define NN 50000
#define NE 800000
#define NG 512
#define DH 128
#define NV 100
#define LN_EPS 1e-5f

#define SCAN_B 256
#define NBLK ((NN + SCAN_B - 1) / SCAN_B)   // 196
#define CNT_BLKS ((NE + 255) / 256)          // 3125 (1 edge/thread)

// ---------------- scratch (static device globals; zero-init at load) --------
__device__ __nv_bfloat16 g_embW[NV * DH];   // bf16(emb @ W1)
__device__ float  g_dinv[NN];               // rsqrt(deg+1)
__device__ float2 g_nd[NN];                 // {dinv, bitcast(x*DH)}
__device__ int    g_deg[NN];                // self-cleaned in k_fill
__device__ int    g_rs[NN + 1];
__device__ int    g_col[NE];                // packed CSR col list (locality matters!)
__device__ int    g_eslot[NE];              // per-edge slot within dst list
__device__ __nv_bfloat16 g_h1[NN * DH];     // bf16( relu(LN(conv1)) * dinv ) pre-scaled
__device__ __nv_bfloat16 g_ag2bf[NN * DH];  // bf16 layer-2 aggregated input
__device__ float  g_pool[NG * DH];          // self-cleaned in k_out
__device__ float  g_cnt[NG];                // self-cleaned in k_out

// ---------------- helpers ----------------
__device__ __forceinline__ float4 ld4(const float* p) {
    return *reinterpret_cast<const float4*>(p);
}
__device__ __forceinline__ void st4(float* p, float4 v) {
    *reinterpret_cast<float4*>(p) = v;
}
__device__ __forceinline__ void stbf4(__nv_bfloat16* p, float4 v) {
    __nv_bfloat162 a = __floats2bfloat162_rn(v.x, v.y);
    __nv_bfloat162 b = __floats2bfloat162_rn(v.z, v.w);
    uint2 u;
    u.x = *reinterpret_cast<unsigned*>(&a);
    u.y = *reinterpret_cast<unsigned*>(&b);
    *reinterpret_cast<uint2*>(p) = u;
}

#define FMA2(acc, a, b) \
    asm("fma.rn.f32x2 %0, %1, %2, %0;" : "+l"(acc) : "l"(a), "l"(b))
#define ADD2(acc, a) \
    asm("add.rn.f32x2 %0, %0, %1;" : "+l"(acc) : "l"(a))
#define PACK2(out, f) \
    asm("mov.b64 %0, {%1, %1};" : "=l"(out) : "f"(f))
#define UNPACK2(lo, hi, in) \
    asm("mov.b64 {%0, %1}, %2;" : "=f"(lo), "=f"(hi) : "l"(in))

// bf16x4 (uint2) -> two f32x2 pairs via exact shift-expansion (no cvt).
__device__ __forceinline__ void expand_bf4(uint2 u,
                                           unsigned long long& p01,
                                           unsigned long long& p23) {
    unsigned a = u.x << 16;
    unsigned b = u.x & 0xFFFF0000u;
    unsigned c = u.y << 16;
    unsigned d = u.y & 0xFFFF0000u;
    asm("mov.b64 %0, {%1, %2};" : "=l"(p01) : "r"(a), "r"(b));
    asm("mov.b64 %0, {%1, %2};" : "=l"(p23) : "r"(c), "r"(d));
}
__device__ __forceinline__ float4 expand_bf4_f4(uint2 u) {
    float4 r;
    unsigned a = u.x << 16;
    unsigned b = u.x & 0xFFFF0000u;
    unsigned c = u.y << 16;
    unsigned d = u.y & 0xFFFF0000u;
    r.x = __uint_as_float(a);
    r.y = __uint_as_float(b);
    r.z = __uint_as_float(c);
    r.w = __uint_as_float(d);
    return r;
}

// ---------------- kernels ----------------

// blocks [0, CNT_BLKS): count in-degrees + record per-edge slot (coalesced).
// Spare blocks: embW = bf16(emb @ W1).
__global__ void __launch_bounds__(256) k_count_embW(const int* __restrict__ ei,
                                                    const float* __restrict__ emb,
                                                    const float* __restrict__ W1) {
    if (blockIdx.x < CNT_BLKS) {
        int e = blockIdx.x * 256 + threadIdx.x;
        if (e < NE) g_eslot[e] = atomicAdd(&g_deg[ei[NE + e]], 1);
    } else {
        int r = (blockIdx.x - CNT_BLKS) * 2 + (threadIdx.x >> 7);
        int c = threadIdx.x & 127;
        if (r < NV) {
            float acc = 0.f;
#pragma unroll 8
            for (int k = 0; k < DH; k++) acc += emb[r * DH + k] * W1[k * DH + c];
            g_embW[r * DH + c] = __float2bfloat16(acc);
        }
    }
}

// scan (single kernel): each block directly reduces g_deg over its predecessor
// range for the offset, then in-block scan; writes rs/dinv/nd. Does NOT touch
// g_deg (cleaned later by k_fill) — avoids read/clean races across blocks.
__global__ void __launch_bounds__(SCAN_B) k_write(const int* __restrict__ x) {
    int i = blockIdx.x * SCAN_B + threadIdx.x;
    int t = threadIdx.x, lane = t & 31, wid = t >> 5;
    int v = (i < NN) ? g_deg[i] : 0;

    // block offset: strided sum of g_deg[0 .. blockIdx.x*SCAN_B)
    int lim = blockIdx.x * SCAN_B;
    int part = 0;
    for (int j = t; j < lim; j += SCAN_B) part += g_deg[j];
    __shared__ int rs2[8];
#pragma unroll
    for (int o = 16; o > 0; o >>= 1) part += __shfl_xor_sync(0xffffffffu, part, o);
    if (lane == 0) rs2[wid] = part;

    // in-block inclusive scan of v
    int inc = v;
#pragma unroll
    for (int o = 1; o < 32; o <<= 1) {
        int n = __shfl_up_sync(0xffffffffu, inc, o);
        if (lane >= o) inc += n;
    }
    __shared__ int ws[8];
    if (lane == 31) ws[wid] = inc;
    __syncthreads();
    if (wid == 0 && lane < 8) {
        int s = ws[lane];
#pragma unroll
        for (int o = 1; o < 8; o <<= 1) {
            int n = __shfl_up_sync(0xffu, s, o);
            if (lane >= o) s += n;
        }
        ws[lane] = s;
    }
    __shared__ int s_off;
    if (t == 0) {
        int s = 0;
#pragma unroll
        for (int k = 0; k < 8; k++) s += rs2[k];
        s_off = s;
    }
    __syncthreads();
    int excl = inc - v + (wid > 0 ? ws[wid - 1] : 0) + s_off;
    if (i < NN) {
        g_rs[i] = excl;
        float d = rsqrtf((float)v + 1.0f);
        g_dinv[i] = d;
        g_nd[i] = make_float2(d, __int_as_float(x[i] * DH));
    }
    if (i == 0) g_rs[NN] = NE;
}

// CSR fill: atomic-free (slot precomputed); also self-cleans g_deg.
__global__ void k_fill(const int* __restrict__ ei) {
    int e = blockIdx.x * blockDim.x + threadIdx.x;
    if (e < NN) g_deg[e] = 0;               // self-clean for next call
    if (e < NE) {
        int s = ei[e];
        int d = ei[NE + e];
        g_col[g_rs[d] + g_eslot[e]] = s;
    }
}

// layer 1: warp per node, 4 accumulator chains (2-deep FMA dependency).
__global__ void __launch_bounds__(256) k_agg1(const float* __restrict__ b1,
                                              const float* __restrict__ g1,
                                              const float* __restrict__ be1) {
    int w = (blockIdx.x * blockDim.x + threadIdx.x) >> 5;
    int lane = threadIdx.x & 31;
    if (w >= NN) return;
    const int i = w;
    float2 ndi = g_nd[i];
    float di = ndi.x;
    int xoff = __float_as_int(ndi.y);       // x*DH
    unsigned long long accA01 = 0, accA23 = 0, accB01 = 0, accB23 = 0;
    {   // self with weight di (chain A)
        uint2 u = *reinterpret_cast<const uint2*>(g_embW + xoff + lane * 4);
        unsigned long long p01, p23, dp;
        expand_bf4(u, p01, p23);
        PACK2(dp, di);
        FMA2(accA01, p01, dp);
        FMA2(accA23, p23, dp);
    }
    int beg = g_rs[i], end = g_rs[i + 1];
    int j = beg;
    for (; j + 4 <= end; j += 4) {
        int s0 = g_col[j], s1 = g_col[j + 1], s2 = g_col[j + 2], s3 = g_col[j + 3];
        float2 n0 = g_nd[s0], n1 = g_nd[s1], n2 = g_nd[s2], n3 = g_nd[s3];
        uint2 u0 = *reinterpret_cast<const uint2*>(g_embW + __float_as_int(n0.y) + lane * 4);
        uint2 u1 = *reinterpret_cast<const uint2*>(g_embW + __float_as_int(n1.y) + lane * 4);
        uint2 u2 = *reinterpret_cast<const uint2*>(g_embW + __float_as_int(n2.y) + lane * 4);
        uint2 u3 = *reinterpret_cast<const uint2*>(g_embW + __float_as_int(n3.y) + lane * 4);
        unsigned long long p01, p23, dp;
        expand_bf4(u0, p01, p23); PACK2(dp, n0.x);
        FMA2(accA01, p01, dp); FMA2(accA23, p23, dp);
        expand_bf4(u1, p01, p23); PACK2(dp, n1.x);
        FMA2(accB01, p01, dp); FMA2(accB23, p23, dp);
        expand_bf4(u2, p01, p23); PACK2(dp, n2.x);
        FMA2(accA01, p01, dp); FMA2(accA23, p23, dp);
        expand_bf4(u3, p01, p23); PACK2(dp, n3.x);
        FMA2(accB01, p01, dp); FMA2(accB23, p23, dp);
    }
    for (; j < end; j++) {
        int s = g_col[j];
        float2 ns = g_nd[s];
        uint2 u = *reinterpret_cast<const uint2*>(g_embW + __float_as_int(ns.y) + lane * 4);
        unsigned long long p01, p23, dp;
        expand_bf4(u, p01, p23); PACK2(dp, ns.x);
        FMA2(accA01, p01, dp); FMA2(accA23, p23, dp);
    }
    ADD2(accA01, accB01);
    ADD2(accA23, accB23);
    float4 acc;
    UNPACK2(acc.x, acc.y, accA01);
    UNPACK2(acc.z, acc.w, accA23);
    float4 bb = ld4(b1 + lane * 4);
    acc.x = acc.x * di + bb.x; acc.y = acc.y * di + bb.y;
    acc.z = acc.z * di + bb.z; acc.w = acc.w * di + bb.w;
    float s1v = acc.x + acc.y + acc.z + acc.w;
    float s2v = acc.x * acc.x + acc.y * acc.y + acc.z * acc.z + acc.w * acc.w;
#pragma unroll
    for (int o = 16; o > 0; o >>= 1) {
        s1v += __shfl_xor_sync(0xffffffffu, s1v, o);
        s2v += __shfl_xor_sync(0xffffffffu, s2v, o);
    }
    float mu = s1v * (1.0f / DH);
    float var = s2v * (1.0f / DH) - mu * mu;
    float rs = rsqrtf(var + LN_EPS);
    float4 gg = ld4(g1 + lane * 4);
    float4 be = ld4(be1 + lane * 4);
    float4 vo;
    vo.x = fmaxf((acc.x - mu) * rs * gg.x + be.x, 0.f) * di;
    vo.y = fmaxf((acc.y - mu) * rs * gg.y + be.y, 0.f) * di;
    vo.z = fmaxf((acc.z - mu) * rs * gg.z + be.z, 0.f) * di;
    vo.w = fmaxf((acc.w - mu) * rs * gg.w + be.w, 0.f) * di;
    stbf4(g_h1 + i * DH + lane * 4, vo);
}

// layer 2 aggregation: warp per node, 4 accumulator chains -> bf16 out.
__global__ void __launch_bounds__(256) k_agg2() {
    int w = (blockIdx.x * blockDim.x + threadIdx.x) >> 5;
    int lane = threadIdx.x & 31;
    if (w >= NN) return;
    const int i = w;
    float di = g_dinv[i];
    unsigned long long accA01, accA23, accB01 = 0, accB23 = 0;
    {   // self (pre-scaled by di), chain A
        uint2 u = *reinterpret_cast<const uint2*>(g_h1 + i * DH + lane * 4);
        expand_bf4(u, accA01, accA23);
    }
    int beg = g_rs[i], end = g_rs[i + 1];
    int j = beg;
    for (; j + 4 <= end; j += 4) {
        int s0 = g_col[j], s1 = g_col[j + 1], s2 = g_col[j + 2], s3 = g_col[j + 3];
        uint2 u0 = *reinterpret_cast<const uint2*>(g_h1 + s0 * DH + lane * 4);
        uint2 u1 = *reinterpret_cast<const uint2*>(g_h1 + s1 * DH + lane * 4);
        uint2 u2 = *reinterpret_cast<const uint2*>(g_h1 + s2 * DH + lane * 4);
        uint2 u3 = *reinterpret_cast<const uint2*>(g_h1 + s3 * DH + lane * 4);
        unsigned long long p01, p23;
        expand_bf4(u0, p01, p23); ADD2(accA01, p01); ADD2(accA23, p23);
        expand_bf4(u1, p01, p23); ADD2(accB01, p01); ADD2(accB23, p23);
        expand_bf4(u2, p01, p23); ADD2(accA01, p01); ADD2(accA23, p23);
        expand_bf4(u3, p01, p23); ADD2(accB01, p01); ADD2(accB23, p23);
    }
    for (; j < end; j++) {
        uint2 u = *reinterpret_cast<const uint2*>(g_h1 + g_col[j] * DH + lane * 4);
        unsigned long long p01, p23;
        expand_bf4(u, p01, p23); ADD2(accA01, p01); ADD2(accA23, p23);
    }
    ADD2(accA01, accB01);
    ADD2(accA23, accB23);
    float4 acc;
    UNPACK2(acc.x, acc.y, accA01);
    UNPACK2(acc.z, acc.w, accA23);
    acc.x *= di; acc.y *= di; acc.z *= di; acc.w *= di;
    stbf4(g_ag2bf + i * DH + lane * 4, acc);
}

// layer-2 GEMM (bf16 ag2 @ W2, f32x2 packed) + bias + LN + ReLU + pool atomics.
__global__ void __launch_bounds__(256) k_gemm2(const float* __restrict__ W2,
                                               const float* __restrict__ b2,
                                               const float* __restrict__ g2,
                                               const float* __restrict__ be2,
                                               const int* __restrict__ batch) {
    __shared__ float sh[32 * DH];
    int tid = threadIdx.x;
    int nb = blockIdx.x * 32;
#pragma unroll
    for (int q = 0; q < 4; q++) {
        int idx = tid + q * 256;            // uint2 index (4 bf16 each)
        int row = idx >> 5;
        int ci = idx & 31;
        int n = nb + row;
        float4 v;
        if (n < NN) {
            uint2 u = *reinterpret_cast<const uint2*>(g_ag2bf + n * DH + ci * 4);
            v = expand_bf4_f4(u);
        } else {
            v = make_float4(0, 0, 0, 0);
        }
        st4(sh + idx * 4, v);
    }
    __syncthreads();
    int w = tid >> 5, lane = tid & 31;
    unsigned long long a0x = 0, a0z = 0, a1x = 0, a1z = 0,
                       a2x = 0, a2z = 0, a3x = 0, a3z = 0;
    const float* shb = sh + (w * 4) * DH;
#pragma unroll 4
    for (int k = 0; k < DH; k++) {
        ulonglong2 wv = *reinterpret_cast<const ulonglong2*>(W2 + k * DH + lane * 4);
        float h0 = shb[k], h1 = shb[DH + k], h2 = shb[2 * DH + k], h3 = shb[3 * DH + k];
        unsigned long long hh0, hh1, hh2, hh3;
        PACK2(hh0, h0); PACK2(hh1, h1); PACK2(hh2, h2); PACK2(hh3, h3);
        FMA2(a0x, wv.x, hh0); FMA2(a0z, wv.y, hh0);
        FMA2(a1x, wv.x, hh1); FMA2(a1z, wv.y, hh1);
        FMA2(a2x, wv.x, hh2); FMA2(a2z, wv.y, hh2);
        FMA2(a3x, wv.x, hh3); FMA2(a3z, wv.y, hh3);
    }
    float4 accs[4];
    UNPACK2(accs[0].x, accs[0].y, a0x); UNPACK2(accs[0].z, accs[0].w, a0z);
    UNPACK2(accs[1].x, accs[1].y, a1x); UNPACK2(accs[1].z, accs[1].w, a1z);
    UNPACK2(accs[2].x, accs[2].y, a2x); UNPACK2(accs[2].z, accs[2].w, a2z);
    UNPACK2(accs[3].x, accs[3].y, a3x); UNPACK2(accs[3].z, accs[3].w, a3z);

    float4 bb = ld4(b2 + lane * 4);
    float4 gg = ld4(g2 + lane * 4);
    float4 be = ld4(be2 + lane * 4);
    float4 vv[4];
    int gid[4];
#pragma unroll
    for (int q = 0; q < 4; q++) {
        int n = nb + w * 4 + q;
        float4 v = accs[q];
        v.x += bb.x; v.y += bb.y; v.z += bb.z; v.w += bb.w;
        float s1v = v.x + v.y + v.z + v.w;
        float s2v = v.x * v.x + v.y * v.y + v.z * v.z + v.w * v.w;
#pragma unroll
        for (int o = 16; o > 0; o >>= 1) {
            s1v += __shfl_xor_sync(0xffffffffu, s1v, o);
            s2v += __shfl_xor_sync(0xffffffffu, s2v, o);
        }
        float mu = s1v * (1.0f / DH);
        float var = s2v * (1.0f / DH) - mu * mu;
        float rs = rsqrtf(var + LN_EPS);
        vv[q].x = fmaxf((v.x - mu) * rs * gg.x + be.x, 0.f);
        vv[q].y = fmaxf((v.y - mu) * rs * gg.y + be.y, 0.f);
        vv[q].z = fmaxf((v.z - mu) * rs * gg.z + be.z, 0.f);
        vv[q].w = fmaxf((v.w - mu) * rs * gg.w + be.w, 0.f);
        gid[q] = (n < NN) ? __ldg(batch + n) : -1;
    }
    float4 run = vv[0];
    int rg = gid[0];
    float rc = 1.f;
#pragma unroll
    for (int q = 1; q < 4; q++) {
        if (gid[q] == rg) {
            run.x += vv[q].x; run.y += vv[q].y; run.z += vv[q].z; run.w += vv[q].w;
            rc += 1.f;
        } else {
            if (rg >= 0) {
                float* p = g_pool + rg * DH + lane * 4;
                atomicAdd(p + 0, run.x); atomicAdd(p + 1, run.y);
                atomicAdd(p + 2, run.z); atomicAdd(p + 3, run.w);
                if (lane == 0) atomicAdd(&g_cnt[rg], rc);
            }
            run = vv[q]; rg = gid[q]; rc = 1.f;
        }
    }
    if (rg >= 0) {
        float* p = g_pool + rg * DH + lane * 4;
        atomicAdd(p + 0, run.x); atomicAdd(p + 1, run.y);
        atomicAdd(p + 2, run.z); atomicAdd(p + 3, run.w);
        if (lane == 0) atomicAdd(&g_cnt[rg], rc);
    }
}

// final: out[g] = mean-pooled dot fcW + fcb; self-cleans pool/cnt for next call.
__global__ void k_out(const float* __restrict__ fcW, const float* __restrict__ fcb,
                      float* __restrict__ out) {
    int w = (blockIdx.x * blockDim.x + threadIdx.x) >> 5;
    int lane = threadIdx.x & 31;
    if (w >= NG) return;
    float* prow = g_pool + w * DH + lane * 4;
    float4 p = ld4(prow);
    float4 f = ld4(fcW + lane * 4);
    float part = p.x * f.x + p.y * f.y + p.z * f.z + p.w * f.w;
#pragma unroll
    for (int o = 16; o > 0; o >>= 1) part += __shfl_xor_sync(0xffffffffu, part, o);
    if (lane == 0) {
        float c = g_cnt[w];
        out[w] = part / fmaxf(c, 1.0f) + fcb[0];
        g_cnt[w] = 0.f;                        // self-clean
    }
    st4(prow, make_float4(0.f, 0.f, 0.f, 0.f)); // self-clean
}

// ---------------- launch ----------------
extern "C" void kernel_launch(void* const* d_in, const int* in_sizes, int n_in,
                              void* d_out, int out_size) {
    const int*   x     = (const int*)d_in[0];
    const int*   ei    = (const int*)d_in[1];
    const int*   batch = (const int*)d_in[2];
    const float* emb   = (const float*)d_in[3];
    const float* W1    = (const float*)d_in[4];
    const float* b1    = (const float*)d_in[5];
    const float* g1    = (const float*)d_in[6];
    const float* be1   = (const float*)d_in[7];
    const float* W2    = (const float*)d_in[8];
    const float* b2    = (const float*)d_in[9];
    const float* g2    = (const float*)d_in[10];
    const float* be2   = (const float*)d_in[11];
    const float* fcW   = (const float*)d_in[12];
    const float* fcb   = (const float*)d_in[13];
    float* out = (float*)d_out;

    k_count_embW<<<CNT_BLKS + (NV + 1) / 2, 256>>>(ei, emb, W1);
    k_write<<<NBLK, SCAN_B>>>(x);
    k_fill<<<CNT_BLKS, 256>>>(ei);
    k_agg1<<<(NN * 32 + 255) / 256, 256>>>(b1, g1, be1);
    k_agg2<<<(NN * 32 + 255) / 256, 256>>>();
    k_gemm2<<<(NN + 31) / 32, 256>>>(W2, b2, g2, be2, batch);
    k_out<<<(NG * 32 + 255) / 256, 256>>>(fcW, fcb, out);
}

// round 15
// speedup vs baseline: 1.0145x; 1.0145x over previous
#include <cuda_runtime.h>
#include <cuda_bf16.h>

#define NN 50000
#define NE 800000
#define NG 512
#define DH 128
#define NV 100
#define LN_EPS 1e-5f

#define SCAN_B 256
#define NBLK ((NN + SCAN_B - 1) / SCAN_B)   // 196
#define CNT_BLKS ((NE + 255) / 256)          // 3125 (1 edge/thread)

// ---------------- scratch (static device globals; zero-init at load) --------
__device__ __nv_bfloat16 g_embW[NV * DH];   // bf16(emb @ W1)
__device__ float  g_dinv[NN];               // rsqrt(deg+1)
__device__ float2 g_nd[NN];                 // {dinv, bitcast(x*DH)}
__device__ int    g_deg[NN];                // self-cleaned in k_fill
__device__ int    g_rs[NN + 1];
__device__ int    g_col[NE];                // packed CSR col list (locality matters!)
__device__ int    g_eslot[NE];              // per-edge slot within dst list
__device__ __nv_bfloat16 g_h1[NN * DH];     // bf16( relu(LN(conv1)) * dinv ) pre-scaled
__device__ __nv_bfloat16 g_ag2bf[NN * DH];  // bf16 layer-2 aggregated input
__device__ float  g_pool[NG * DH];          // self-cleaned in k_out
__device__ float  g_cnt[NG];                // self-cleaned in k_out

// ---------------- helpers ----------------
__device__ __forceinline__ float4 ld4(const float* p) {
    return *reinterpret_cast<const float4*>(p);
}
__device__ __forceinline__ void st4(float* p, float4 v) {
    *reinterpret_cast<float4*>(p) = v;
}
__device__ __forceinline__ void stbf4(__nv_bfloat16* p, float4 v) {
    __nv_bfloat162 a = __floats2bfloat162_rn(v.x, v.y);
    __nv_bfloat162 b = __floats2bfloat162_rn(v.z, v.w);
    uint2 u;
    u.x = *reinterpret_cast<unsigned*>(&a);
    u.y = *reinterpret_cast<unsigned*>(&b);
    *reinterpret_cast<uint2*>(p) = u;
}

#define FMA2(acc, a, b) \
    asm("fma.rn.f32x2 %0, %1, %2, %0;" : "+l"(acc) : "l"(a), "l"(b))
#define ADD2(acc, a) \
    asm("add.rn.f32x2 %0, %0, %1;" : "+l"(acc) : "l"(a))
#define PACK2(out, f) \
    asm("mov.b64 %0, {%1, %1};" : "=l"(out) : "f"(f))
#define UNPACK2(lo, hi, in) \
    asm("mov.b64 {%0, %1}, %2;" : "=f"(lo), "=f"(hi) : "l"(in))

// bf16x4 (uint2) -> two f32x2 pairs via exact shift-expansion (no cvt).
__device__ __forceinline__ void expand_bf4(uint2 u,
                                           unsigned long long& p01,
                                           unsigned long long& p23) {
    unsigned a = u.x << 16;
    unsigned b = u.x & 0xFFFF0000u;
    unsigned c = u.y << 16;
    unsigned d = u.y & 0xFFFF0000u;
    asm("mov.b64 %0, {%1, %2};" : "=l"(p01) : "r"(a), "r"(b));
    asm("mov.b64 %0, {%1, %2};" : "=l"(p23) : "r"(c), "r"(d));
}
__device__ __forceinline__ float4 expand_bf4_f4(uint2 u) {
    float4 r;
    unsigned a = u.x << 16;
    unsigned b = u.x & 0xFFFF0000u;
    unsigned c = u.y << 16;
    unsigned d = u.y & 0xFFFF0000u;
    r.x = __uint_as_float(a);
    r.y = __uint_as_float(b);
    r.z = __uint_as_float(c);
    r.w = __uint_as_float(d);
    return r;
}

// ---------------- kernels ----------------

// blocks [0, CNT_BLKS): count in-degrees + record per-edge slot (coalesced).
// Spare blocks: embW = bf16(emb @ W1).
__global__ void __launch_bounds__(256) k_count_embW(const int* __restrict__ ei,
                                                    const float* __restrict__ emb,
                                                    const float* __restrict__ W1) {
    if (blockIdx.x < CNT_BLKS) {
        int e = blockIdx.x * 256 + threadIdx.x;
        if (e < NE) g_eslot[e] = atomicAdd(&g_deg[ei[NE + e]], 1);
    } else {
        int r = (blockIdx.x - CNT_BLKS) * 2 + (threadIdx.x >> 7);
        int c = threadIdx.x & 127;
        if (r < NV) {
            float acc = 0.f;
#pragma unroll 8
            for (int k = 0; k < DH; k++) acc += emb[r * DH + k] * W1[k * DH + c];
            g_embW[r * DH + c] = __float2bfloat16(acc);
        }
    }
}

// scan (single kernel): each block directly reduces g_deg over its predecessor
// range for the offset, then in-block scan; writes rs/dinv/nd. Does NOT touch
// g_deg (cleaned later by k_fill).
__global__ void __launch_bounds__(SCAN_B) k_write(const int* __restrict__ x) {
    int i = blockIdx.x * SCAN_B + threadIdx.x;
    int t = threadIdx.x, lane = t & 31, wid = t >> 5;
    int v = (i < NN) ? g_deg[i] : 0;

    // block offset: strided sum of g_deg[0 .. blockIdx.x*SCAN_B)
    int lim = blockIdx.x * SCAN_B;
    int part = 0;
    for (int j = t; j < lim; j += SCAN_B) part += g_deg[j];
    __shared__ int rs2[8];
#pragma unroll
    for (int o = 16; o > 0; o >>= 1) part += __shfl_xor_sync(0xffffffffu, part, o);
    if (lane == 0) rs2[wid] = part;

    // in-block inclusive scan of v
    int inc = v;
#pragma unroll
    for (int o = 1; o < 32; o <<= 1) {
        int n = __shfl_up_sync(0xffffffffu, inc, o);
        if (lane >= o) inc += n;
    }
    __shared__ int ws[8];
    if (lane == 31) ws[wid] = inc;
    __syncthreads();
    if (wid == 0 && lane < 8) {
        int s = ws[lane];
#pragma unroll
        for (int o = 1; o < 8; o <<= 1) {
            int n = __shfl_up_sync(0xffu, s, o);
            if (lane >= o) s += n;
        }
        ws[lane] = s;
    }
    __shared__ int s_off;
    if (t == 0) {
        int s = 0;
#pragma unroll
        for (int k = 0; k < 8; k++) s += rs2[k];
        s_off = s;
    }
    __syncthreads();
    int excl = inc - v + (wid > 0 ? ws[wid - 1] : 0) + s_off;
    if (i < NN) {
        g_rs[i] = excl;
        float d = rsqrtf((float)v + 1.0f);
        g_dinv[i] = d;
        g_nd[i] = make_float2(d, __int_as_float(x[i] * DH));
    }
    if (i == 0) g_rs[NN] = NE;
}

// CSR fill: atomic-free (slot precomputed); also self-cleans g_deg.
__global__ void k_fill(const int* __restrict__ ei) {
    int e = blockIdx.x * blockDim.x + threadIdx.x;
    if (e < NN) g_deg[e] = 0;               // self-clean for next call
    if (e < NE) {
        int s = ei[e];
        int d = ei[NE + e];
        g_col[g_rs[d] + g_eslot[e]] = s;
    }
}

// layer 1: warp per node (R13 single-chain body — measured best).
__global__ void __launch_bounds__(256) k_agg1(const float* __restrict__ b1,
                                              const float* __restrict__ g1,
                                              const float* __restrict__ be1) {
    int w = (blockIdx.x * blockDim.x + threadIdx.x) >> 5;
    int lane = threadIdx.x & 31;
    if (w >= NN) return;
    const int i = w;
    float2 ndi = g_nd[i];
    float di = ndi.x;
    int xoff = __float_as_int(ndi.y);       // x*DH
    unsigned long long acc01 = 0, acc23 = 0;
    {   // self with weight di
        uint2 u = *reinterpret_cast<const uint2*>(g_embW + xoff + lane * 4);
        unsigned long long p01, p23, dp;
        expand_bf4(u, p01, p23);
        PACK2(dp, di);
        FMA2(acc01, p01, dp);
        FMA2(acc23, p23, dp);
    }
    int beg = g_rs[i], end = g_rs[i + 1];
    int j = beg;
    for (; j + 4 <= end; j += 4) {
        int s0 = g_col[j], s1 = g_col[j + 1], s2 = g_col[j + 2], s3 = g_col[j + 3];
        float2 n0 = g_nd[s0], n1 = g_nd[s1], n2 = g_nd[s2], n3 = g_nd[s3];
        uint2 u0 = *reinterpret_cast<const uint2*>(g_embW + __float_as_int(n0.y) + lane * 4);
        uint2 u1 = *reinterpret_cast<const uint2*>(g_embW + __float_as_int(n1.y) + lane * 4);
        uint2 u2 = *reinterpret_cast<const uint2*>(g_embW + __float_as_int(n2.y) + lane * 4);
        uint2 u3 = *reinterpret_cast<const uint2*>(g_embW + __float_as_int(n3.y) + lane * 4);
        unsigned long long p01, p23, dp;
        expand_bf4(u0, p01, p23); PACK2(dp, n0.x);
        FMA2(acc01, p01, dp); FMA2(acc23, p23, dp);
        expand_bf4(u1, p01, p23); PACK2(dp, n1.x);
        FMA2(acc01, p01, dp); FMA2(acc23, p23, dp);
        expand_bf4(u2, p01, p23); PACK2(dp, n2.x);
        FMA2(acc01, p01, dp); FMA2(acc23, p23, dp);
        expand_bf4(u3, p01, p23); PACK2(dp, n3.x);
        FMA2(acc01, p01, dp); FMA2(acc23, p23, dp);
    }
    for (; j < end; j++) {
        int s = g_col[j];
        float2 ns = g_nd[s];
        uint2 u = *reinterpret_cast<const uint2*>(g_embW + __float_as_int(ns.y) + lane * 4);
        unsigned long long p01, p23, dp;
        expand_bf4(u, p01, p23); PACK2(dp, ns.x);
        FMA2(acc01, p01, dp); FMA2(acc23, p23, dp);
    }
    float4 acc;
    UNPACK2(acc.x, acc.y, acc01);
    UNPACK2(acc.z, acc.w, acc23);
    float4 bb = ld4(b1 + lane * 4);
    acc.x = acc.x * di + bb.x; acc.y = acc.y * di + bb.y;
    acc.z = acc.z * di + bb.z; acc.w = acc.w * di + bb.w;
    float s1v = acc.x + acc.y + acc.z + acc.w;
    float s2v = acc.x * acc.x + acc.y * acc.y + acc.z * acc.z + acc.w * acc.w;
#pragma unroll
    for (int o = 16; o > 0; o >>= 1) {
        s1v += __shfl_xor_sync(0xffffffffu, s1v, o);
        s2v += __shfl_xor_sync(0xffffffffu, s2v, o);
    }
    float mu = s1v * (1.0f / DH);
    float var = s2v * (1.0f / DH) - mu * mu;
    float rs = rsqrtf(var + LN_EPS);
    float4 gg = ld4(g1 + lane * 4);
    float4 be = ld4(be1 + lane * 4);
    float4 vo;
    vo.x = fmaxf((acc.x - mu) * rs * gg.x + be.x, 0.f) * di;
    vo.y = fmaxf((acc.y - mu) * rs * gg.y + be.y, 0.f) * di;
    vo.z = fmaxf((acc.z - mu) * rs * gg.z + be.z, 0.f) * di;
    vo.w = fmaxf((acc.w - mu) * rs * gg.w + be.w, 0.f) * di;
    stbf4(g_h1 + i * DH + lane * 4, vo);
}

// layer 2 aggregation: warp per node (R13 single-chain body) -> bf16 out.
__global__ void __launch_bounds__(256) k_agg2() {
    int w = (blockIdx.x * blockDim.x + threadIdx.x) >> 5;
    int lane = threadIdx.x & 31;
    if (w >= NN) return;
    const int i = w;
    float di = g_dinv[i];
    unsigned long long acc01, acc23;
    {   // self (pre-scaled by di)
        uint2 u = *reinterpret_cast<const uint2*>(g_h1 + i * DH + lane * 4);
        expand_bf4(u, acc01, acc23);
    }
    int beg = g_rs[i], end = g_rs[i + 1];
    int j = beg;
    for (; j + 4 <= end; j += 4) {
        int s0 = g_col[j], s1 = g_col[j + 1], s2 = g_col[j + 2], s3 = g_col[j + 3];
        uint2 u0 = *reinterpret_cast<const uint2*>(g_h1 + s0 * DH + lane * 4);
        uint2 u1 = *reinterpret_cast<const uint2*>(g_h1 + s1 * DH + lane * 4);
        uint2 u2 = *reinterpret_cast<const uint2*>(g_h1 + s2 * DH + lane * 4);
        uint2 u3 = *reinterpret_cast<const uint2*>(g_h1 + s3 * DH + lane * 4);
        unsigned long long p01, p23;
        expand_bf4(u0, p01, p23); ADD2(acc01, p01); ADD2(acc23, p23);
        expand_bf4(u1, p01, p23); ADD2(acc01, p01); ADD2(acc23, p23);
        expand_bf4(u2, p01, p23); ADD2(acc01, p01); ADD2(acc23, p23);
        expand_bf4(u3, p01, p23); ADD2(acc01, p01); ADD2(acc23, p23);
    }
    for (; j < end; j++) {
        uint2 u = *reinterpret_cast<const uint2*>(g_h1 + g_col[j] * DH + lane * 4);
        unsigned long long p01, p23;
        expand_bf4(u, p01, p23); ADD2(acc01, p01); ADD2(acc23, p23);
    }
    float4 acc;
    UNPACK2(acc.x, acc.y, acc01);
    UNPACK2(acc.z, acc.w, acc23);
    acc.x *= di; acc.y *= di; acc.z *= di; acc.w *= di;
    stbf4(g_ag2bf + i * DH + lane * 4, acc);
}

// layer-2 GEMM (bf16 ag2 @ W2, f32x2 packed) + bias + LN + ReLU + pool atomics.
__global__ void __launch_bounds__(256) k_gemm2(const float* __restrict__ W2,
                                               const float* __restrict__ b2,
                                               const float* __restrict__ g2,
                                               const float* __restrict__ be2,
                                               const int* __restrict__ batch) {
    __shared__ float sh[32 * DH];
    int tid = threadIdx.x;
    int nb = blockIdx.x * 32;
#pragma unroll
    for (int q = 0; q < 4; q++) {
        int idx = tid + q * 256;            // uint2 index (4 bf16 each)
        int row = idx >> 5;
        int ci = idx & 31;
        int n = nb + row;
        float4 v;
        if (n < NN) {
            uint2 u = *reinterpret_cast<const uint2*>(g_ag2bf + n * DH + ci * 4);
            v = expand_bf4_f4(u);
        } else {
            v = make_float4(0, 0, 0, 0);
        }
        st4(sh + idx * 4, v);
    }
    __syncthreads();
    int w = tid >> 5, lane = tid & 31;
    unsigned long long a0x = 0, a0z = 0, a1x = 0, a1z = 0,
                       a2x = 0, a2z = 0, a3x = 0, a3z = 0;
    const float* shb = sh + (w * 4) * DH;
#pragma unroll 4
    for (int k = 0; k < DH; k++) {
        ulonglong2 wv = *reinterpret_cast<const ulonglong2*>(W2 + k * DH + lane * 4);
        float h0 = shb[k], h1 = shb[DH + k], h2 = shb[2 * DH + k], h3 = shb[3 * DH + k];
        unsigned long long hh0, hh1, hh2, hh3;
        PACK2(hh0, h0); PACK2(hh1, h1); PACK2(hh2, h2); PACK2(hh3, h3);
        FMA2(a0x, wv.x, hh0); FMA2(a0z, wv.y, hh0);
        FMA2(a1x, wv.x, hh1); FMA2(a1z, wv.y, hh1);
        FMA2(a2x, wv.x, hh2); FMA2(a2z, wv.y, hh2);
        FMA2(a3x, wv.x, hh3); FMA2(a3z, wv.y, hh3);
    }
    float4 accs[4];
    UNPACK2(accs[0].x, accs[0].y, a0x); UNPACK2(accs[0].z, accs[0].w, a0z);
    UNPACK2(accs[1].x, accs[1].y, a1x); UNPACK2(accs[1].z, accs[1].w, a1z);
    UNPACK2(accs[2].x, accs[2].y, a2x); UNPACK2(accs[2].z, accs[2].w, a2z);
    UNPACK2(accs[3].x, accs[3].y, a3x); UNPACK2(accs[3].z, accs[3].w, a3z);

    float4 bb = ld4(b2 + lane * 4);
    float4 gg = ld4(g2 + lane * 4);
    float4 be = ld4(be2 + lane * 4);
    float4 vv[4];
    int gid[4];
#pragma unroll
    for (int q = 0; q < 4; q++) {
        int n = nb + w * 4 + q;
        float4 v = accs[q];
        v.x += bb.x; v.y += bb.y; v.z += bb.z; v.w += bb.w;
        float s1v = v.x + v.y + v.z + v.w;
        float s2v = v.x * v.x + v.y * v.y + v.z * v.z + v.w * v.w;
#pragma unroll
        for (int o = 16; o > 0; o >>= 1) {
            s1v += __shfl_xor_sync(0xffffffffu, s1v, o);
            s2v += __shfl_xor_sync(0xffffffffu, s2v, o);
        }
        float mu = s1v * (1.0f / DH);
        float var = s2v * (1.0f / DH) - mu * mu;
        float rs = rsqrtf(var + LN_EPS);
        vv[q].x = fmaxf((v.x - mu) * rs * gg.x + be.x, 0.f);
        vv[q].y = fmaxf((v.y - mu) * rs * gg.y + be.y, 0.f);
        vv[q].z = fmaxf((v.z - mu) * rs * gg.z + be.z, 0.f);
        vv[q].w = fmaxf((v.w - mu) * rs * gg.w + be.w, 0.f);
        gid[q] = (n < NN) ? __ldg(batch + n) : -1;
    }
    float4 run = vv[0];
    int rg = gid[0];
    float rc = 1.f;
#pragma unroll
    for (int q = 1; q < 4; q++) {
        if (gid[q] == rg) {
            run.x += vv[q].x; run.y += vv[q].y; run.z += vv[q].z; run.w += vv[q].w;
            rc += 1.f;
        } else {
            if (rg >= 0) {
                float* p = g_pool + rg * DH + lane * 4;
                atomicAdd(p + 0, run.x); atomicAdd(p + 1, run.y);
                atomicAdd(p + 2, run.z); atomicAdd(p + 3, run.w);
                if (lane == 0) atomicAdd(&g_cnt[rg], rc);
            }
            run = vv[q]; rg = gid[q]; rc = 1.f;
        }
    }
    if (rg >= 0) {
        float* p = g_pool + rg * DH + lane * 4;
        atomicAdd(p + 0, run.x); atomicAdd(p + 1, run.y);
        atomicAdd(p + 2, run.z); atomicAdd(p + 3, run.w);
        if (lane == 0) atomicAdd(&g_cnt[rg], rc);
    }
}

// final: out[g] = mean-pooled dot fcW + fcb; self-cleans pool/cnt for next call.
__global__ void k_out(const float* __restrict__ fcW, const float* __restrict__ fcb,
                      float* __restrict__ out) {
    int w = (blockIdx.x * blockDim.x + threadIdx.x) >> 5;
    int lane = threadIdx.x & 31;
    if (w >= NG) return;
    float* prow = g_pool + w * DH + lane * 4;
    float4 p = ld4(prow);
    float4 f = ld4(fcW + lane * 4);
    float part = p.x * f.x + p.y * f.y + p.z * f.z + p.w * f.w;
#pragma unroll
    for (int o = 16; o > 0; o >>= 1) part += __shfl_xor_sync(0xffffffffu, part, o);
    if (lane == 0) {
        float c = g_cnt[w];
        out[w] = part / fmaxf(c, 1.0f) + fcb[0];
        g_cnt[w] = 0.f;                        // self-clean
    }
    st4(prow, make_float4(0.f, 0.f, 0.f, 0.f)); // self-clean
}

// ---------------- launch ----------------
extern "C" void kernel_launch(void* const* d_in, const int* in_sizes, int n_in,
                              void* d_out, int out_size) {
    const int*   x     = (const int*)d_in[0];
    const int*   ei    = (const int*)d_in[1];
    const int*   batch = (const int*)d_in[2];
    const float* emb   = (const float*)d_in[3];
    const float* W1    = (const float*)d_in[4];
    const float* b1    = (const float*)d_in[5];
    const float* g1    = (const float*)d_in[6];
    const float* be1   = (const float*)d_in[7];
    const float* W2    = (const float*)d_in[8];
    const float* b2    = (const float*)d_in[9];
    const float* g2    = (const float*)d_in[10];
    const float* be2   = (const float*)d_in[11];
    const float* fcW   = (const float*)d_in[12];
    const float* fcb   = (const float*)d_in[13];
    float* out = (float*)d_out;

    k_count_embW<<<CNT_BLKS + (NV + 1) / 2, 256>>>(ei, emb, W1);
    k_write<<<NBLK, SCAN_B>>>(x);
    k_fill<<<CNT_BLKS, 256>>>(ei);
    k_agg1<<<(NN * 32 + 255) / 256, 256>>>(b1, g1, be1);
    k_agg2<<<(NN * 32 + 255) / 256, 256>>>();
    k_gemm2<<<(NN + 31) / 32, 256>>>(W2, b2, g2, be2, batch);
    k_out<<<(NG * 32 + 255) / 256, 256>>>(fcW, fcb, out);
}

// round 16
// speedup vs baseline: 1.0552x; 1.0401x over previous
#include <cuda_runtime.h>
#include <cuda_bf16.h>

#define NN 50000
#define NE 800000
#define NG 512
#define DH 128
#define NV 100
#define LN_EPS 1e-5f

#define SCAN_B 256
#define NBLK ((NN + SCAN_B - 1) / SCAN_B)   // 196
#define CNT_BLKS ((NE + 255) / 256)          // 3125 (1 edge/thread)

// ---------------- scratch (static device globals; zero-init at load) --------
__device__ __nv_bfloat16 g_embW[NV * DH];   // bf16(emb @ W1)
__device__ float  g_dinv[NN];               // rsqrt(deg+1)
__device__ float2 g_nd[NN];                 // {dinv, bitcast(x*DH)}
__device__ int    g_deg[NN];                // self-cleaned in k_write
__device__ int    g_rs[NN + 1];
__device__ int    g_col[NE];                // packed CSR col list (locality matters!)
__device__ int    g_eslot[NE];              // per-edge slot within dst list
__device__ int    g_bsum[NBLK];
__device__ __nv_bfloat16 g_h1[NN * DH];     // bf16( relu(LN(conv1)) * dinv ) pre-scaled
__device__ __nv_bfloat16 g_ag2bf[NN * DH];  // bf16 layer-2 aggregated input
__device__ float  g_pool[NG * DH];          // self-cleaned in k_out
__device__ float  g_cnt[NG];                // self-cleaned in k_out

// ---------------- helpers ----------------
__device__ __forceinline__ float4 ld4(const float* p) {
    return *reinterpret_cast<const float4*>(p);
}
__device__ __forceinline__ void st4(float* p, float4 v) {
    *reinterpret_cast<float4*>(p) = v;
}
__device__ __forceinline__ void stbf4(__nv_bfloat16* p, float4 v) {
    __nv_bfloat162 a = __floats2bfloat162_rn(v.x, v.y);
    __nv_bfloat162 b = __floats2bfloat162_rn(v.z, v.w);
    uint2 u;
    u.x = *reinterpret_cast<unsigned*>(&a);
    u.y = *reinterpret_cast<unsigned*>(&b);
    *reinterpret_cast<uint2*>(p) = u;
}

#define FMA2(acc, a, b) \
    asm("fma.rn.f32x2 %0, %1, %2, %0;" : "+l"(acc) : "l"(a), "l"(b))
#define ADD2(acc, a) \
    asm("add.rn.f32x2 %0, %0, %1;" : "+l"(acc) : "l"(a))
#define PACK2(out, f) \
    asm("mov.b64 %0, {%1, %1};" : "=l"(out) : "f"(f))
#define UNPACK2(lo, hi, in) \
    asm("mov.b64 {%0, %1}, %2;" : "=f"(lo), "=f"(hi) : "l"(in))

// bf16x4 (uint2) -> two f32x2 pairs via exact shift-expansion (no cvt).
__device__ __forceinline__ void expand_bf4(uint2 u,
                                           unsigned long long& p01,
                                           unsigned long long& p23) {
    unsigned a = u.x << 16;
    unsigned b = u.x & 0xFFFF0000u;
    unsigned c = u.y << 16;
    unsigned d = u.y & 0xFFFF0000u;
    asm("mov.b64 %0, {%1, %2};" : "=l"(p01) : "r"(a), "r"(b));
    asm("mov.b64 %0, {%1, %2};" : "=l"(p23) : "r"(c), "r"(d));
}
__device__ __forceinline__ float4 expand_bf4_f4(uint2 u) {
    float4 r;
    unsigned a = u.x << 16;
    unsigned b = u.x & 0xFFFF0000u;
    unsigned c = u.y << 16;
    unsigned d = u.y & 0xFFFF0000u;
    r.x = __uint_as_float(a);
    r.y = __uint_as_float(b);
    r.z = __uint_as_float(c);
    r.w = __uint_as_float(d);
    return r;
}

// ---------------- kernels ----------------

// blocks [0, CNT_BLKS): count in-degrees + record per-edge slot (coalesced).
// Spare blocks: embW = bf16(emb @ W1).
__global__ void __launch_bounds__(256) k_count_embW(const int* __restrict__ ei,
                                                    const float* __restrict__ emb,
                                                    const float* __restrict__ W1) {
    if (blockIdx.x < CNT_BLKS) {
        int e = blockIdx.x * 256 + threadIdx.x;
        if (e < NE) g_eslot[e] = atomicAdd(&g_deg[ei[NE + e]], 1);
    } else {
        int r = (blockIdx.x - CNT_BLKS) * 2 + (threadIdx.x >> 7);
        int c = threadIdx.x & 127;
        if (r < NV) {
            float acc = 0.f;
#pragma unroll 8
            for (int k = 0; k < DH; k++) acc += emb[r * DH + k] * W1[k * DH + c];
            g_embW[r * DH + c] = __float2bfloat16(acc);
        }
    }
}

// phase 1: per-block degree sums
__global__ void __launch_bounds__(SCAN_B) k_partial() {
    int i = blockIdx.x * SCAN_B + threadIdx.x;
    int lane = threadIdx.x & 31, wid = threadIdx.x >> 5;
    int v = (i < NN) ? g_deg[i] : 0;
#pragma unroll
    for (int o = 16; o > 0; o >>= 1) v += __shfl_xor_sync(0xffffffffu, v, o);
    __shared__ int ws[8];
    if (lane == 0) ws[wid] = v;
    __syncthreads();
    if (threadIdx.x == 0) {
        int s = 0;
#pragma unroll
        for (int k = 0; k < 8; k++) s += ws[k];
        g_bsum[blockIdx.x] = s;
    }
}

// phase 2: per-block predecessor reduce + in-block scan; write rs/dinv/nd.
__global__ void __launch_bounds__(SCAN_B) k_write(const int* __restrict__ x) {
    int i = blockIdx.x * SCAN_B + threadIdx.x;
    int t = threadIdx.x, lane = t & 31, wid = t >> 5;
    int v = (i < NN) ? g_deg[i] : 0;
    if (i < NN) g_deg[i] = 0;               // self-clean for next call

    __shared__ int rs2[8];
    int contrib = (t < blockIdx.x) ? g_bsum[t] : 0;
    int red = contrib;
#pragma unroll
    for (int o = 16; o > 0; o >>= 1) red += __shfl_xor_sync(0xffffffffu, red, o);
    if (lane == 0) rs2[wid] = red;

    int inc = v;
#pragma unroll
    for (int o = 1; o < 32; o <<= 1) {
        int n = __shfl_up_sync(0xffffffffu, inc, o);
        if (lane >= o) inc += n;
    }
    __shared__ int ws[8];
    if (lane == 31) ws[wid] = inc;
    __syncthreads();
    if (wid == 0 && lane < 8) {
        int s = ws[lane];
#pragma unroll
        for (int o = 1; o < 8; o <<= 1) {
            int n = __shfl_up_sync(0xffu, s, o);
            if (lane >= o) s += n;
        }
        ws[lane] = s;
    }
    __shared__ int s_off;
    if (t == 0) {
        int s = 0;
#pragma unroll
        for (int k = 0; k < 8; k++) s += rs2[k];
        s_off = s;
    }
    __syncthreads();
    int excl = inc - v + (wid > 0 ? ws[wid - 1] : 0) + s_off;
    if (i < NN) {
        g_rs[i] = excl;
        float d = rsqrtf((float)v + 1.0f);
        g_dinv[i] = d;
        g_nd[i] = make_float2(d, __int_as_float(x[i] * DH));
    }
    if (i == 0) g_rs[NN] = NE;
}

// CSR fill: atomic-free, slot precomputed in count pass.
__global__ void k_fill(const int* __restrict__ ei) {
    int e = blockIdx.x * blockDim.x + threadIdx.x;
    if (e < NE) {
        int s = ei[e];
        int d = ei[NE + e];
        g_col[g_rs[d] + g_eslot[e]] = s;
    }
}

// layer 1: warp per node (single-chain body — measured best).
__global__ void __launch_bounds__(256) k_agg1(const float* __restrict__ b1,
                                              const float* __restrict__ g1,
                                              const float* __restrict__ be1) {
    int w = (blockIdx.x * blockDim.x + threadIdx.x) >> 5;
    int lane = threadIdx.x & 31;
    if (w >= NN) return;
    const int i = w;
    float2 ndi = g_nd[i];
    float di = ndi.x;
    int xoff = __float_as_int(ndi.y);       // x*DH
    unsigned long long acc01 = 0, acc23 = 0;
    {   // self with weight di
        uint2 u = *reinterpret_cast<const uint2*>(g_embW + xoff + lane * 4);
        unsigned long long p01, p23, dp;
        expand_bf4(u, p01, p23);
        PACK2(dp, di);
        FMA2(acc01, p01, dp);
        FMA2(acc23, p23, dp);
    }
    int beg = g_rs[i], end = g_rs[i + 1];
    int j = beg;
    for (; j + 4 <= end; j += 4) {
        int s0 = g_col[j], s1 = g_col[j + 1], s2 = g_col[j + 2], s3 = g_col[j + 3];
        float2 n0 = g_nd[s0], n1 = g_nd[s1], n2 = g_nd[s2], n3 = g_nd[s3];
        uint2 u0 = *reinterpret_cast<const uint2*>(g_embW + __float_as_int(n0.y) + lane * 4);
        uint2 u1 = *reinterpret_cast<const uint2*>(g_embW + __float_as_int(n1.y) + lane * 4);
        uint2 u2 = *reinterpret_cast<const uint2*>(g_embW + __float_as_int(n2.y) + lane * 4);
        uint2 u3 = *reinterpret_cast<const uint2*>(g_embW + __float_as_int(n3.y) + lane * 4);
        unsigned long long p01, p23, dp;
        expand_bf4(u0, p01, p23); PACK2(dp, n0.x);
        FMA2(acc01, p01, dp); FMA2(acc23, p23, dp);
        expand_bf4(u1, p01, p23); PACK2(dp, n1.x);
        FMA2(acc01, p01, dp); FMA2(acc23, p23, dp);
        expand_bf4(u2, p01, p23); PACK2(dp, n2.x);
        FMA2(acc01, p01, dp); FMA2(acc23, p23, dp);
        expand_bf4(u3, p01, p23); PACK2(dp, n3.x);
        FMA2(acc01, p01, dp); FMA2(acc23, p23, dp);
    }
    for (; j < end; j++) {
        int s = g_col[j];
        float2 ns = g_nd[s];
        uint2 u = *reinterpret_cast<const uint2*>(g_embW + __float_as_int(ns.y) + lane * 4);
        unsigned long long p01, p23, dp;
        expand_bf4(u, p01, p23); PACK2(dp, ns.x);
        FMA2(acc01, p01, dp); FMA2(acc23, p23, dp);
    }
    float4 acc;
    UNPACK2(acc.x, acc.y, acc01);
    UNPACK2(acc.z, acc.w, acc23);
    float4 bb = ld4(b1 + lane * 4);
    acc.x = acc.x * di + bb.x; acc.y = acc.y * di + bb.y;
    acc.z = acc.z * di + bb.z; acc.w = acc.w * di + bb.w;
    float s1v = acc.x + acc.y + acc.z + acc.w;
    float s2v = acc.x * acc.x + acc.y * acc.y + acc.z * acc.z + acc.w * acc.w;
#pragma unroll
    for (int o = 16; o > 0; o >>= 1) {
        s1v += __shfl_xor_sync(0xffffffffu, s1v, o);
        s2v += __shfl_xor_sync(0xffffffffu, s2v, o);
    }
    float mu = s1v * (1.0f / DH);
    float var = s2v * (1.0f / DH) - mu * mu;
    float rs = rsqrtf(var + LN_EPS);
    float4 gg = ld4(g1 + lane * 4);
    float4 be = ld4(be1 + lane * 4);
    float4 vo;
    vo.x = fmaxf((acc.x - mu) * rs * gg.x + be.x, 0.f) * di;
    vo.y = fmaxf((acc.y - mu) * rs * gg.y + be.y, 0.f) * di;
    vo.z = fmaxf((acc.z - mu) * rs * gg.z + be.z, 0.f) * di;
    vo.w = fmaxf((acc.w - mu) * rs * gg.w + be.w, 0.f) * di;
    stbf4(g_h1 + i * DH + lane * 4, vo);
}

// layer 2 aggregation: warp per node, 8-wide gather unroll (MLP), single chain.
__global__ void __launch_bounds__(256) k_agg2() {
    int w = (blockIdx.x * blockDim.x + threadIdx.x) >> 5;
    int lane = threadIdx.x & 31;
    if (w >= NN) return;
    const int i = w;
    float di = g_dinv[i];
    unsigned long long acc01, acc23;
    {   // self (pre-scaled by di)
        uint2 u = *reinterpret_cast<const uint2*>(g_h1 + i * DH + lane * 4);
        expand_bf4(u, acc01, acc23);
    }
    int beg = g_rs[i], end = g_rs[i + 1];
    int j = beg;
    for (; j + 8 <= end; j += 8) {
        int s0 = g_col[j],     s1 = g_col[j + 1], s2 = g_col[j + 2], s3 = g_col[j + 3];
        int s4 = g_col[j + 4], s5 = g_col[j + 5], s6 = g_col[j + 6], s7 = g_col[j + 7];
        uint2 u0 = *reinterpret_cast<const uint2*>(g_h1 + s0 * DH + lane * 4);
        uint2 u1 = *reinterpret_cast<const uint2*>(g_h1 + s1 * DH + lane * 4);
        uint2 u2 = *reinterpret_cast<const uint2*>(g_h1 + s2 * DH + lane * 4);
        uint2 u3 = *reinterpret_cast<const uint2*>(g_h1 + s3 * DH + lane * 4);
        uint2 u4 = *reinterpret_cast<const uint2*>(g_h1 + s4 * DH + lane * 4);
        uint2 u5 = *reinterpret_cast<const uint2*>(g_h1 + s5 * DH + lane * 4);
        uint2 u6 = *reinterpret_cast<const uint2*>(g_h1 + s6 * DH + lane * 4);
        uint2 u7 = *reinterpret_cast<const uint2*>(g_h1 + s7 * DH + lane * 4);
        unsigned long long p01, p23;
        expand_bf4(u0, p01, p23); ADD2(acc01, p01); ADD2(acc23, p23);
        expand_bf4(u1, p01, p23); ADD2(acc01, p01); ADD2(acc23, p23);
        expand_bf4(u2, p01, p23); ADD2(acc01, p01); ADD2(acc23, p23);
        expand_bf4(u3, p01, p23); ADD2(acc01, p01); ADD2(acc23, p23);
        expand_bf4(u4, p01, p23); ADD2(acc01, p01); ADD2(acc23, p23);
        expand_bf4(u5, p01, p23); ADD2(acc01, p01); ADD2(acc23, p23);
        expand_bf4(u6, p01, p23); ADD2(acc01, p01); ADD2(acc23, p23);
        expand_bf4(u7, p01, p23); ADD2(acc01, p01); ADD2(acc23, p23);
    }
    for (; j + 4 <= end; j += 4) {
        int s0 = g_col[j], s1 = g_col[j + 1], s2 = g_col[j + 2], s3 = g_col[j + 3];
        uint2 u0 = *reinterpret_cast<const uint2*>(g_h1 + s0 * DH + lane * 4);
        uint2 u1 = *reinterpret_cast<const uint2*>(g_h1 + s1 * DH + lane * 4);
        uint2 u2 = *reinterpret_cast<const uint2*>(g_h1 + s2 * DH + lane * 4);
        uint2 u3 = *reinterpret_cast<const uint2*>(g_h1 + s3 * DH + lane * 4);
        unsigned long long p01, p23;
        expand_bf4(u0, p01, p23); ADD2(acc01, p01); ADD2(acc23, p23);
        expand_bf4(u1, p01, p23); ADD2(acc01, p01); ADD2(acc23, p23);
        expand_bf4(u2, p01, p23); ADD2(acc01, p01); ADD2(acc23, p23);
        expand_bf4(u3, p01, p23); ADD2(acc01, p01); ADD2(acc23, p23);
    }
    for (; j < end; j++) {
        uint2 u = *reinterpret_cast<const uint2*>(g_h1 + g_col[j] * DH + lane * 4);
        unsigned long long p01, p23;
        expand_bf4(u, p01, p23); ADD2(acc01, p01); ADD2(acc23, p23);
    }
    float4 acc;
    UNPACK2(acc.x, acc.y, acc01);
    UNPACK2(acc.z, acc.w, acc23);
    acc.x *= di; acc.y *= di; acc.z *= di; acc.w *= di;
    stbf4(g_ag2bf + i * DH + lane * 4, acc);
}

// layer-2 GEMM (bf16 ag2 @ W2, f32x2 packed) + bias + LN + ReLU + pool atomics.
__global__ void __launch_bounds__(256) k_gemm2(const float* __restrict__ W2,
                                               const float* __restrict__ b2,
                                               const float* __restrict__ g2,
                                               const float* __restrict__ be2,
                                               const int* __restrict__ batch) {
    __shared__ float sh[32 * DH];
    int tid = threadIdx.x;
    int nb = blockIdx.x * 32;
#pragma unroll
    for (int q = 0; q < 4; q++) {
        int idx = tid + q * 256;            // uint2 index (4 bf16 each)
        int row = idx >> 5;
        int ci = idx & 31;
        int n = nb + row;
        float4 v;
        if (n < NN) {
            uint2 u = *reinterpret_cast<const uint2*>(g_ag2bf + n * DH + ci * 4);
            v = expand_bf4_f4(u);
        } else {
            v = make_float4(0, 0, 0, 0);
        }
        st4(sh + idx * 4, v);
    }
    __syncthreads();
    int w = tid >> 5, lane = tid & 31;
    unsigned long long a0x = 0, a0z = 0, a1x = 0, a1z = 0,
                       a2x = 0, a2z = 0, a3x = 0, a3z = 0;
    const float* shb = sh + (w * 4) * DH;
#pragma unroll 4
    for (int k = 0; k < DH; k++) {
        ulonglong2 wv = *reinterpret_cast<const ulonglong2*>(W2 + k * DH + lane * 4);
        float h0 = shb[k], h1 = shb[DH + k], h2 = shb[2 * DH + k], h3 = shb[3 * DH + k];
        unsigned long long hh0, hh1, hh2, hh3;
        PACK2(hh0, h0); PACK2(hh1, h1); PACK2(hh2, h2); PACK2(hh3, h3);
        FMA2(a0x, wv.x, hh0); FMA2(a0z, wv.y, hh0);
        FMA2(a1x, wv.x, hh1); FMA2(a1z, wv.y, hh1);
        FMA2(a2x, wv.x, hh2); FMA2(a2z, wv.y, hh2);
        FMA2(a3x, wv.x, hh3); FMA2(a3z, wv.y, hh3);
    }
    float4 accs[4];
    UNPACK2(accs[0].x, accs[0].y, a0x); UNPACK2(accs[0].z, accs[0].w, a0z);
    UNPACK2(accs[1].x, accs[1].y, a1x); UNPACK2(accs[1].z, accs[1].w, a1z);
    UNPACK2(accs[2].x, accs[2].y, a2x); UNPACK2(accs[2].z, accs[2].w, a2z);
    UNPACK2(accs[3].x, accs[3].y, a3x); UNPACK2(accs[3].z, accs[3].w, a3z);

    float4 bb = ld4(b2 + lane * 4);
    float4 gg = ld4(g2 + lane * 4);
    float4 be = ld4(be2 + lane * 4);
    float4 vv[4];
    int gid[4];
#pragma unroll
    for (int q = 0; q < 4; q++) {
        int n = nb + w * 4 + q;
        float4 v = accs[q];
        v.x += bb.x; v.y += bb.y; v.z += bb.z; v.w += bb.w;
        float s1v = v.x + v.y + v.z + v.w;
        float s2v = v.x * v.x + v.y * v.y + v.z * v.z + v.w * v.w;
#pragma unroll
        for (int o = 16; o > 0; o >>= 1) {
            s1v += __shfl_xor_sync(0xffffffffu, s1v, o);
            s2v += __shfl_xor_sync(0xffffffffu, s2v, o);
        }
        float mu = s1v * (1.0f / DH);
        float var = s2v * (1.0f / DH) - mu * mu;
        float rs = rsqrtf(var + LN_EPS);
        vv[q].x = fmaxf((v.x - mu) * rs * gg.x + be.x, 0.f);
        vv[q].y = fmaxf((v.y - mu) * rs * gg.y + be.y, 0.f);
        vv[q].z = fmaxf((v.z - mu) * rs * gg.z + be.z, 0.f);
        vv[q].w = fmaxf((v.w - mu) * rs * gg.w + be.w, 0.f);
        gid[q] = (n < NN) ? __ldg(batch + n) : -1;
    }
    float4 run = vv[0];
    int rg = gid[0];
    float rc = 1.f;
#pragma unroll
    for (int q = 1; q < 4; q++) {
        if (gid[q] == rg) {
            run.x += vv[q].x; run.y += vv[q].y; run.z += vv[q].z; run.w += vv[q].w;
            rc += 1.f;
        } else {
            if (rg >= 0) {
                float* p = g_pool + rg * DH + lane * 4;
                atomicAdd(p + 0, run.x); atomicAdd(p + 1, run.y);
                atomicAdd(p + 2, run.z); atomicAdd(p + 3, run.w);
                if (lane == 0) atomicAdd(&g_cnt[rg], rc);
            }
            run = vv[q]; rg = gid[q]; rc = 1.f;
        }
    }
    if (rg >= 0) {
        float* p = g_pool + rg * DH + lane * 4;
        atomicAdd(p + 0, run.x); atomicAdd(p + 1, run.y);
        atomicAdd(p + 2, run.z); atomicAdd(p + 3, run.w);
        if (lane == 0) atomicAdd(&g_cnt[rg], rc);
    }
}

// final: out[g] = mean-pooled dot fcW + fcb; self-cleans pool/cnt for next call.
__global__ void k_out(const float* __restrict__ fcW, const float* __restrict__ fcb,
                      float* __restrict__ out) {
    int w = (blockIdx.x * blockDim.x + threadIdx.x) >> 5;
    int lane = threadIdx.x & 31;
    if (w >= NG) return;
    float* prow = g_pool + w * DH + lane * 4;
    float4 p = ld4(prow);
    float4 f = ld4(fcW + lane * 4);
    float part = p.x * f.x + p.y * f.y + p.z * f.z + p.w * f.w;
#pragma unroll
    for (int o = 16; o > 0; o >>= 1) part += __shfl_xor_sync(0xffffffffu, part, o);
    if (lane == 0) {
        float c = g_cnt[w];
        out[w] = part / fmaxf(c, 1.0f) + fcb[0];
        g_cnt[w] = 0.f;                        // self-clean
    }
    st4(prow, make_float4(0.f, 0.f, 0.f, 0.f)); // self-clean
}

// ---------------- launch ----------------
extern "C" void kernel_launch(void* const* d_in, const int* in_sizes, int n_in,
                              void* d_out, int out_size) {
    const int*   x     = (const int*)d_in[0];
    const int*   ei    = (const int*)d_in[1];
    const int*   batch = (const int*)d_in[2];
    const float* emb   = (const float*)d_in[3];
    const float* W1    = (const float*)d_in[4];
    const float* b1    = (const float*)d_in[5];
    const float* g1    = (const float*)d_in[6];
    const float* be1   = (const float*)d_in[7];
    const float* W2    = (const float*)d_in[8];
    const float* b2    = (const float*)d_in[9];
    const float* g2    = (const float*)d_in[10];
    const float* be2   = (const float*)d_in[11];
    const float* fcW   = (const float*)d_in[12];
    const float* fcb   = (const float*)d_in[13];
    float* out = (float*)d_out;

    k_count_embW<<<CNT_BLKS + (NV + 1) / 2, 256>>>(ei, emb, W1);
    k_partial<<<NBLK, SCAN_B>>>();
    k_write<<<NBLK, SCAN_B>>>(x);
    k_fill<<<CNT_BLKS, 256>>>(ei);
    k_agg1<<<(NN * 32 + 255) / 256, 256>>>(b1, g1, be1);
    k_agg2<<<(NN * 32 + 255) / 256, 256>>>();
    k_gemm2<<<(NN + 31) / 32, 256>>>(W2, b2, g2, be2, batch);
    k_out<<<(NG * 32 + 255) / 256, 256>>>(fcW, fcb, out);
}